// round 7
// baseline (speedup 1.0000x reference)
#include <cuda_runtime.h>
#include <cuda_bf16.h>
#include <cstdint>

#define UD 10000
#define ID 12000
#define IPAD 12032   // 94*128
#define UPAD 10112   // 79*128

// ---------------- scratch ----------------
__device__ __align__(16) uint16_t g_iT_h[64 * IPAD], g_iT_l[64 * IPAD];  // item_sv^T bf16 hi/lo [k][i]
__device__ __align__(16) uint16_t g_uT_h[64 * UPAD], g_uT_l[64 * UPAD];  // user_sv^T bf16 hi/lo [k][u]
__device__ __align__(16) float    g_lp[3][(size_t)UD * 64];              // K1 partials [u][k]
__device__ __align__(16) float    g_rp[3][(size_t)ID * 64];              // K2 partials [i][k]
__device__ __align__(16) uint16_t g_l_h[UPAD * 64], g_l_l[UPAD * 64];    // left*invL bf16 [u][k]
__device__ __align__(16) uint16_t g_r_h[IPAD * 64], g_r_l[IPAD * 64];    // right^T bf16 [i][k]

// ---------------- helpers ----------------
__device__ __forceinline__ uint32_t smem_u32(const void* p) {
    uint32_t a;
    asm("{ .reg .u64 t; cvta.to.shared.u64 t, %1; cvt.u32.u64 %0, t; }" : "=r"(a) : "l"(p));
    return a;
}
__device__ __forceinline__ void split2(float x0, float x1, uint32_t& h, uint32_t& l) {
    asm("cvt.rn.bf16x2.f32 %0, %1, %2;" : "=r"(h) : "f"(x1), "f"(x0));
    float r0 = x0 - __uint_as_float(h << 16);
    float r1 = x1 - __uint_as_float(h & 0xffff0000u);
    asm("cvt.rn.bf16x2.f32 %0, %1, %2;" : "=r"(l) : "f"(r1), "f"(r0));
}
__device__ __forceinline__ void split1(float x, uint16_t& h, uint16_t& l) {
    uint32_t hh, ll;
    asm("cvt.rn.bf16x2.f32 %0, %1, %2;" : "=r"(hh) : "f"(0.f), "f"(x));
    float r = x - __uint_as_float(hh << 16);
    asm("cvt.rn.bf16x2.f32 %0, %1, %2;" : "=r"(ll) : "f"(0.f), "f"(r));
    h = (uint16_t)hh; l = (uint16_t)ll;
}
__device__ __forceinline__ void ldm4(uint32_t* r, uint32_t a) {
    asm volatile("ldmatrix.sync.aligned.m8n8.x4.shared.b16 {%0,%1,%2,%3},[%4];"
                 : "=r"(r[0]), "=r"(r[1]), "=r"(r[2]), "=r"(r[3]) : "r"(a));
}
__device__ __forceinline__ void ldm4t(uint32_t* r, uint32_t a) {
    asm volatile("ldmatrix.sync.aligned.m8n8.x4.trans.shared.b16 {%0,%1,%2,%3},[%4];"
                 : "=r"(r[0]), "=r"(r[1]), "=r"(r[2]), "=r"(r[3]) : "r"(a));
}
__device__ __forceinline__ void mma_bf16(float* d, const uint32_t* a, uint32_t b0, uint32_t b1) {
    asm volatile("mma.sync.aligned.m16n8k16.row.col.f32.bf16.bf16.f32 "
                 "{%0,%1,%2,%3},{%4,%5,%6,%7},{%8,%9},{%0,%1,%2,%3};"
                 : "+f"(d[0]), "+f"(d[1]), "+f"(d[2]), "+f"(d[3])
                 : "r"(a[0]), "r"(a[1]), "r"(a[2]), "r"(a[3]), "r"(b0), "r"(b1));
}
#define CP16(dst, src) \
    asm volatile("cp.async.cg.shared.global [%0],[%1],16;" :: "r"(dst), "l"(src) : "memory")
#define CPCOMMIT() asm volatile("cp.async.commit_group;" ::: "memory")
#define CPWAIT0()  asm volatile("cp.async.wait_group 0;" ::: "memory")

// ---------------- prep: tiled transpose + bf16 split ----------------
__global__ __launch_bounds__(256) void p_item(const float* __restrict__ isv) {
    __shared__ float st[64][65];
    const int t = threadIdx.x, i0 = blockIdx.x * 64;
#pragma unroll
    for (int q = 0; q < 16; q++) {
        int idx = t + q * 256;
        int il = idx >> 6, k = idx & 63, gi = i0 + il;
        st[il][k] = (gi < ID) ? isv[(size_t)gi * 64 + k] : 0.f;
    }
    __syncthreads();
#pragma unroll
    for (int q = 0; q < 16; q++) {
        int idx = t + q * 256;
        int k = idx >> 6, il = idx & 63;
        uint16_t h, l; split1(st[il][k], h, l);
        g_iT_h[(size_t)k * IPAD + i0 + il] = h;
        g_iT_l[(size_t)k * IPAD + i0 + il] = l;
    }
}
__global__ __launch_bounds__(256) void p_user(const float* __restrict__ usv) {
    __shared__ float st[64][65];
    const int t = threadIdx.x, u0 = blockIdx.x * 64;
#pragma unroll
    for (int q = 0; q < 16; q++) {
        int idx = t + q * 256;
        int ul = idx >> 6, k = idx & 63, gu = u0 + ul;
        st[ul][k] = (gu < UD) ? usv[(size_t)gu * 64 + k] : 0.f;
    }
    __syncthreads();
#pragma unroll
    for (int q = 0; q < 16; q++) {
        int idx = t + q * 256;
        int k = idx >> 6, ul = idx & 63;
        uint16_t h, l; split1(st[ul][k], h, l);
        g_uT_h[(size_t)k * UPAD + u0 + ul] = h;
        g_uT_l[(size_t)k * UPAD + u0 + ul] = l;
    }
}

// ---------------- K1: g_lp[s] = norm_adj @ item_sv  (M=128u, N=64k, Kchunk=32i) ----------------
// dyn smem 61440: Ah[b] @ b*10240, Al[b] @ 20480+b*10240, Bh[b] @ 40960+b*5120, Bl[b] @ 51200+b*5120
__global__ __launch_bounds__(256, 2) void k1_mma(const float* __restrict__ A) {
    extern __shared__ __align__(16) char sm[];
    const int t = threadIdx.x, lane = t & 31, w = t >> 5;
    const uint32_t sb = smem_u32(sm);
    const int u0 = blockIdx.x * 128, ibase0 = blockIdx.y * 4000;
    const int m0 = (w >> 1) * 32, n0 = (w & 1) * 32;
    const uint32_t aoff = (uint32_t)(m0 + (lane & 15)) * 80 + ((lane >> 4) << 4);
    const uint32_t boff = (uint32_t)(n0 + (lane & 15)) * 80 + ((lane >> 4) << 4);
    const int brow = t >> 2, bc8 = (t & 3) << 3;

    // A loader geometry: thread -> (row = t>>1, 16 consecutive i at (t&1)*16)
    const int arow = t >> 1, acolf = (t & 1) * 16;
    const bool aok = (u0 + arow) < UD;
    const float* arp = A + (size_t)(u0 + arow) * ID + acolf;

    float acc[2][4][4];
#pragma unroll
    for (int a = 0; a < 2; a++)
#pragma unroll
        for (int b = 0; b < 4; b++)
#pragma unroll
            for (int cc = 0; cc < 4; cc++) acc[a][b][cc] = 0.f;

    float4 av[4];

    auto LDGA = [&](int c) {
        const int ib = ibase0 + c * 32;
#pragma unroll
        for (int j = 0; j < 4; j++)
            av[j] = aok ? *(const float4*)(arp + ib + j * 4)
                        : make_float4(0.f, 0.f, 0.f, 0.f);
    };
    auto CPB = [&](int c, int b) {
        const int ib = ibase0 + c * 32;
        const uint32_t d0 = sb + 40960 + b * 5120 + brow * 80 + ((t & 3) << 4);
        const uint32_t d1 = sb + 51200 + b * 5120 + brow * 80 + ((t & 3) << 4);
        CP16(d0, (const void*)(g_iT_h + (size_t)brow * IPAD + ib + bc8));
        CP16(d1, (const void*)(g_iT_l + (size_t)brow * IPAD + ib + bc8));
        CPCOMMIT();
    };
    auto STSA = [&](int b) {
        uint32_t hw[8], lw[8];
#pragma unroll
        for (int j = 0; j < 4; j++) {
            split2(av[j].x, av[j].y, hw[2 * j], lw[2 * j]);
            split2(av[j].z, av[j].w, hw[2 * j + 1], lw[2 * j + 1]);
        }
        char* ab = sm + b * 10240 + arow * 80 + (t & 1) * 32;
        char* al = sm + 20480 + b * 10240 + arow * 80 + (t & 1) * 32;
        *(uint4*)ab        = make_uint4(hw[0], hw[1], hw[2], hw[3]);
        *(uint4*)(ab + 16) = make_uint4(hw[4], hw[5], hw[6], hw[7]);
        *(uint4*)al        = make_uint4(lw[0], lw[1], lw[2], lw[3]);
        *(uint4*)(al + 16) = make_uint4(lw[4], lw[5], lw[6], lw[7]);
    };

    LDGA(0); CPB(0, 0); STSA(0);
    CPWAIT0();
    __syncthreads();

    for (int c = 0; c < 125; c++) {
        const int b = c & 1;
        if (c + 1 < 125) { LDGA(c + 1); CPB(c + 1, b ^ 1); }
        const uint32_t bah = sb + b * 10240,        bal = sb + 20480 + b * 10240;
        const uint32_t bbh = sb + 40960 + b * 5120, bbl = sb + 51200 + b * 5120;
#pragma unroll
        for (int ks = 0; ks < 2; ks++) {
            uint32_t bh[2][4], bl[2][4], ah[2][4], al[2][4];
#pragma unroll
            for (int p = 0; p < 2; p++) {
                ldm4(bh[p], bbh + boff + p * 1280 + ks * 32);
                ldm4(bl[p], bbl + boff + p * 1280 + ks * 32);
            }
#pragma unroll
            for (int mi = 0; mi < 2; mi++) {
                ldm4(ah[mi], bah + aoff + mi * 1280 + ks * 32);
                ldm4(al[mi], bal + aoff + mi * 1280 + ks * 32);
            }
#pragma unroll
            for (int mi = 0; mi < 2; mi++)
#pragma unroll
                for (int nt = 0; nt < 4; nt++) {
                    int p = nt >> 1, j = nt & 1;
                    mma_bf16(acc[mi][nt], ah[mi], bh[p][j], bh[p][j + 2]);
                    mma_bf16(acc[mi][nt], ah[mi], bl[p][j], bl[p][j + 2]);
                    mma_bf16(acc[mi][nt], al[mi], bh[p][j], bh[p][j + 2]);
                }
        }
        if (c + 1 < 125) STSA(b ^ 1);
        CPWAIT0();
        __syncthreads();
    }

    float* dst = g_lp[blockIdx.y];
    const int g = lane >> 2, tg = lane & 3;
#pragma unroll
    for (int mi = 0; mi < 2; mi++)
#pragma unroll
        for (int nt = 0; nt < 4; nt++) {
            int row = u0 + m0 + mi * 16 + g;
            int col = n0 + nt * 8 + tg * 2;
            if (row < UD)     *(float2*)(dst + (size_t)row * 64 + col)       = make_float2(acc[mi][nt][0], acc[mi][nt][1]);
            if (row + 8 < UD) *(float2*)(dst + (size_t)(row + 8) * 64 + col) = make_float2(acc[mi][nt][2], acc[mi][nt][3]);
        }
}

// ---------------- K2: g_rp[s][i][k] = adj^T @ user_sv  (M=128i, N=64k, Kchunk=32u) ----------------
// dyn smem 55296: Ah[b] @ b*8704, Al[b] @ 17408+b*8704, Bh[b] @ 34816+b*5120, Bl[b] @ 45056+b*5120
__global__ __launch_bounds__(256, 2) void k2_mma(const float* __restrict__ Adj) {
    extern __shared__ __align__(16) char sm[];
    const int t = threadIdx.x, lane = t & 31, w = t >> 5;
    const uint32_t sb = smem_u32(sm);
    const int i0 = blockIdx.x * 128, ubase0 = blockIdx.y * 3360;
    const int m0 = (w >> 1) * 32, n0 = (w & 1) * 32;
    const uint32_t aofft = (uint32_t)((lane & 7) + ((lane >> 4) << 3)) * 272
                         + (uint32_t)(m0 + (((lane >> 3) & 1) << 3)) * 2;
    const uint32_t boff = (uint32_t)(n0 + (lane & 15)) * 80 + ((lane >> 4) << 4);
    const int brow = t >> 2, bc8 = (t & 3) << 3;

    // A loader geometry: thread -> rows (t>>4)+q*16 (u), 8 consecutive i at (t&15)*8
    const int arow0 = t >> 4, acolf = (t & 15) * 8;
    const bool iok = (i0 + acolf + 8) <= ID;

    float acc[2][4][4];
#pragma unroll
    for (int a = 0; a < 2; a++)
#pragma unroll
        for (int b = 0; b < 4; b++)
#pragma unroll
            for (int cc = 0; cc < 4; cc++) acc[a][b][cc] = 0.f;

    float4 av[2][2];

    auto LDGA = [&](int c) {
        const int ub = ubase0 + c * 32;
#pragma unroll
        for (int q = 0; q < 2; q++) {
            const int gu = ub + arow0 + q * 16;
            const bool ok = iok && (gu < UD);
            const float* p = Adj + (size_t)gu * ID + i0 + acolf;
            av[q][0] = ok ? *(const float4*)p       : make_float4(0.f, 0.f, 0.f, 0.f);
            av[q][1] = ok ? *(const float4*)(p + 4) : make_float4(0.f, 0.f, 0.f, 0.f);
        }
    };
    auto CPB = [&](int c, int b) {
        const int ub = ubase0 + c * 32;
        const uint32_t d0 = sb + 34816 + b * 5120 + brow * 80 + ((t & 3) << 4);
        const uint32_t d1 = sb + 45056 + b * 5120 + brow * 80 + ((t & 3) << 4);
        CP16(d0, (const void*)(g_uT_h + (size_t)brow * UPAD + ub + bc8));
        CP16(d1, (const void*)(g_uT_l + (size_t)brow * UPAD + ub + bc8));
        CPCOMMIT();
    };
    auto STSA = [&](int b) {
#pragma unroll
        for (int q = 0; q < 2; q++) {
            uint32_t hw[4], lw[4];
            split2(av[q][0].x, av[q][0].y, hw[0], lw[0]);
            split2(av[q][0].z, av[q][0].w, hw[1], lw[1]);
            split2(av[q][1].x, av[q][1].y, hw[2], lw[2]);
            split2(av[q][1].z, av[q][1].w, hw[3], lw[3]);
            char* ab = sm + b * 8704 + (arow0 + q * 16) * 272 + (t & 15) * 16;
            char* al = sm + 17408 + b * 8704 + (arow0 + q * 16) * 272 + (t & 15) * 16;
            *(uint4*)ab = make_uint4(hw[0], hw[1], hw[2], hw[3]);
            *(uint4*)al = make_uint4(lw[0], lw[1], lw[2], lw[3]);
        }
    };

    LDGA(0); CPB(0, 0); STSA(0);
    CPWAIT0();
    __syncthreads();

    for (int c = 0; c < 105; c++) {
        const int b = c & 1;
        if (c + 1 < 105) { LDGA(c + 1); CPB(c + 1, b ^ 1); }
        const uint32_t bah = sb + b * 8704,         bal = sb + 17408 + b * 8704;
        const uint32_t bbh = sb + 34816 + b * 5120, bbl = sb + 45056 + b * 5120;
#pragma unroll
        for (int ks = 0; ks < 2; ks++) {
            uint32_t bh[2][4], bl[2][4], ah[2][4], al[2][4];
#pragma unroll
            for (int p = 0; p < 2; p++) {
                ldm4(bh[p], bbh + boff + p * 1280 + ks * 32);
                ldm4(bl[p], bbl + boff + p * 1280 + ks * 32);
            }
#pragma unroll
            for (int mi = 0; mi < 2; mi++) {
                ldm4t(ah[mi], bah + aofft + mi * 32 + ks * 4352);
                ldm4t(al[mi], bal + aofft + mi * 32 + ks * 4352);
            }
#pragma unroll
            for (int mi = 0; mi < 2; mi++)
#pragma unroll
                for (int nt = 0; nt < 4; nt++) {
                    int p = nt >> 1, j = nt & 1;
                    mma_bf16(acc[mi][nt], ah[mi], bh[p][j], bh[p][j + 2]);
                    mma_bf16(acc[mi][nt], ah[mi], bl[p][j], bl[p][j + 2]);
                    mma_bf16(acc[mi][nt], al[mi], bh[p][j], bh[p][j + 2]);
                }
        }
        if (c + 1 < 105) STSA(b ^ 1);
        CPWAIT0();
        __syncthreads();
    }

    float* dst = g_rp[blockIdx.y];
    const int g = lane >> 2, tg = lane & 3;
#pragma unroll
    for (int mi = 0; mi < 2; mi++)
#pragma unroll
        for (int nt = 0; nt < 4; nt++) {
            int row = i0 + m0 + mi * 16 + g;
            int col = n0 + nt * 8 + tg * 2;
            if (row < ID)     *(float2*)(dst + (size_t)row * 64 + col)       = make_float2(acc[mi][nt][0], acc[mi][nt][1]);
            if (row + 8 < ID) *(float2*)(dst + (size_t)(row + 8) * 64 + col) = make_float2(acc[mi][nt][2], acc[mi][nt][3]);
        }
}

// ---------------- reductions + bf16 split ----------------
__global__ __launch_bounds__(256) void red_l(const float* __restrict__ lam) {
    int idx = blockIdx.x * 256 + threadIdx.x;
    if (idx >= UPAD * 64) return;
    int u = idx >> 6;
    float v = 0.f;
    if (u < UD) v = (g_lp[0][idx] + g_lp[1][idx] + g_lp[2][idx]) / lam[idx & 63];
    split1(v, g_l_h[idx], g_l_l[idx]);
}
__global__ __launch_bounds__(256) void red_r() {
    int idx = blockIdx.x * 256 + threadIdx.x;
    if (idx >= IPAD * 64) return;
    int i = idx >> 6;
    float v = 0.f;
    if (i < ID) v = g_rp[0][idx] + g_rp[1][idx] + g_rp[2][idx];
    split1(v, g_r_h[idx], g_r_l[idx]);
}

// ---------------- K3: out[u][i] = g_l @ g_r^T  (M=128u, N=128i, K=64 single pass) ----------------
__global__ __launch_bounds__(256, 2) void k3_mma(float* __restrict__ out) {
    extern __shared__ __align__(16) char sm[];
    const int t = threadIdx.x, lane = t & 31, w = t >> 5;
    const uint32_t sb = smem_u32(sm);
    const int u0 = blockIdx.x * 128, i0 = blockIdx.y * 128;
    const int m0 = (w >> 2) * 64, n0 = (w & 3) * 32;
    const uint32_t abase = (uint32_t)(m0 + (lane & 15)) * 144 + ((lane >> 4) << 4);
    const uint32_t bbase = (uint32_t)(n0 + (lane & 15)) * 144 + ((lane >> 4) << 4);

#pragma unroll
    for (int q = 0; q < 4; q++) {
        int idx = t + q * 256;
        int row = idx >> 3, c8 = (idx & 7) << 3;
        *(uint4*)(sm + row * 144 + c8 * 2)         = *(const uint4*)(g_l_h + (size_t)(u0 + row) * 64 + c8);
        *(uint4*)(sm + 18432 + row * 144 + c8 * 2) = *(const uint4*)(g_l_l + (size_t)(u0 + row) * 64 + c8);
        *(uint4*)(sm + 36864 + row * 144 + c8 * 2) = *(const uint4*)(g_r_h + (size_t)(i0 + row) * 64 + c8);
        *(uint4*)(sm + 55296 + row * 144 + c8 * 2) = *(const uint4*)(g_r_l + (size_t)(i0 + row) * 64 + c8);
    }
    __syncthreads();

    float acc[4][4][4];
#pragma unroll
    for (int a = 0; a < 4; a++)
#pragma unroll
        for (int b = 0; b < 4; b++)
#pragma unroll
            for (int cc = 0; cc < 4; cc++) acc[a][b][cc] = 0.f;

#pragma unroll
    for (int ks = 0; ks < 4; ks++) {
        uint32_t bh[2][4], bl[2][4];
#pragma unroll
        for (int p = 0; p < 2; p++) {
            ldm4(bh[p], sb + 36864 + bbase + p * 2304 + ks * 32);
            ldm4(bl[p], sb + 55296 + bbase + p * 2304 + ks * 32);
        }
#pragma unroll
        for (int mi = 0; mi < 4; mi++) {
            uint32_t ah[4], al[4];
            ldm4(ah, sb + abase + mi * 2304 + ks * 32);
            ldm4(al, sb + 18432 + abase + mi * 2304 + ks * 32);
#pragma unroll
            for (int nt = 0; nt < 4; nt++) {
                int p = nt >> 1, j = nt & 1;
                mma_bf16(acc[mi][nt], ah, bh[p][j], bh[p][j + 2]);
                mma_bf16(acc[mi][nt], ah, bl[p][j], bl[p][j + 2]);
                mma_bf16(acc[mi][nt], al, bh[p][j], bh[p][j + 2]);
            }
        }
    }

    const int g = lane >> 2, tg = lane & 3;
#pragma unroll
    for (int mi = 0; mi < 4; mi++)
#pragma unroll
        for (int nt = 0; nt < 4; nt++) {
            int row = u0 + m0 + mi * 16 + g;
            int col = i0 + n0 + nt * 8 + tg * 2;
            if (col < ID) {
                if (row < UD)     *(float2*)(out + (size_t)row * ID + col)       = make_float2(acc[mi][nt][0], acc[mi][nt][1]);
                if (row + 8 < UD) *(float2*)(out + (size_t)(row + 8) * ID + col) = make_float2(acc[mi][nt][2], acc[mi][nt][3]);
            }
        }
}

// ---------------- launch ----------------
extern "C" void kernel_launch(void* const* d_in, const int* in_sizes, int n_in,
                              void* d_out, int out_size) {
    const float* lambda_mat = (const float*)d_in[0];
    const float* user_sv    = (const float*)d_in[1];
    const float* item_sv    = (const float*)d_in[2];
    const float* adj_mat    = (const float*)d_in[3];
    const float* norm_adj   = (const float*)d_in[4];
    float* out = (float*)d_out;

    cudaFuncSetAttribute(k1_mma, cudaFuncAttributeMaxDynamicSharedMemorySize, 61440);
    cudaFuncSetAttribute(k2_mma, cudaFuncAttributeMaxDynamicSharedMemorySize, 55296);
    cudaFuncSetAttribute(k3_mma, cudaFuncAttributeMaxDynamicSharedMemorySize, 73728);

    p_item<<<IPAD / 64, 256>>>(item_sv);
    p_user<<<UPAD / 64, 256>>>(user_sv);
    k1_mma<<<dim3(79, 3), 256, 61440>>>(norm_adj);
    k2_mma<<<dim3(94, 3), 256, 55296>>>(adj_mat);
    red_l<<<(UPAD * 64) / 256, 256>>>(lambda_mat);
    red_r<<<(IPAD * 64) / 256, 256>>>();
    k3_mma<<<dim3(79, 94), 256, 73728>>>(out);
}